// round 9
// baseline (speedup 1.0000x reference)
#include <cuda_runtime.h>
#include <cstdint>

#define NE 32     // experts
#define NC 64     // rows per expert
#define ND 1024   // d_model
#define NF 4096   // d_ff
#define KSPLIT2 2048              // GEMM2 K-split length

// static scratch (no allocation): h (32MB), rounded x (8MB), GEMM2 partials (16MB)
__device__ float g_h[(size_t)NE * NC * NF];
__device__ float g_x[(size_t)NE * NC * ND];
__device__ float g_p[2][(size_t)NE * NC * ND];

// ---- smem geometry (words): CTA tile 64x256, BK=16, 3 stages ----
#define AST 20                    // A row stride (16 k + 4 pad): frag banks distinct
#define BST 264                   // B row stride (256 n + 8 pad): frag bank = 8tg+g
#define A_W  (64 * AST)           // 1280 words
#define B_W  (16 * BST)           // 4224 words
#define STG_W (A_W + B_W)         // 5504 words = 22016 B; x3 = 66048 B -> 3 CTAs/SM

__device__ __forceinline__ uint32_t smem_u32(const void* p) {
    uint32_t a;
    asm("{ .reg .u64 t; cvta.to.shared.u64 t, %1; cvt.u32.u64 %0, t; }" : "=r"(a) : "l"(p));
    return a;
}
__device__ __forceinline__ uint32_t to_tf32u(float x) {
    uint32_t y; asm("cvt.rna.tf32.f32 %0, %1;" : "=r"(y) : "f"(x)); return y;
}
__device__ __forceinline__ float tanh_fast(float x) {
    float y; asm("tanh.approx.f32 %0, %1;" : "=f"(y) : "f"(x)); return y;
}
__device__ __forceinline__ float gelu_tanh(float v) {
    const float c0 = 0.7978845608028654f;
    const float c1 = 0.044715f;
    float u = c0 * fmaf(c1 * v * v, v, v);
    return 0.5f * v * (1.0f + tanh_fast(u));
}
__device__ __forceinline__ void cp16(uint32_t dst, const void* src) {
    asm volatile("cp.async.cg.shared.global [%0], [%1], 16;" :: "r"(dst), "l"(src));
}
#define CP_COMMIT() asm volatile("cp.async.commit_group;" ::: "memory")
#define CP_WAIT1()  asm volatile("cp.async.wait_group 1;"  ::: "memory")

__device__ __forceinline__ void mma8(float (&c)[4],
                                     uint32_t a0, uint32_t a1, uint32_t a2, uint32_t a3,
                                     uint32_t b0, uint32_t b1) {
    asm volatile("mma.sync.aligned.m16n8k8.row.col.f32.tf32.tf32.f32 "
                 "{%0,%1,%2,%3}, {%4,%5,%6,%7}, {%8,%9}, {%0,%1,%2,%3};"
                 : "+f"(c[0]), "+f"(c[1]), "+f"(c[2]), "+f"(c[3])
                 : "r"(a0), "r"(a1), "r"(a2), "r"(a3), "r"(b0), "r"(b1));
}

// Unified grouped-GEMM: CTA tile 64x256, 4 warps, warp tile 64x64, BK=16,
// 3-stage cp.async pipeline with ONE __syncthreads per slab.
// MODE 0: C = tf32round(gelu(A@B + bias))   (GEMM1 -> g_h)
// MODE 1: C = A@B partial (K-split via blockIdx.z)  (GEMM2 -> g_p)
// A pre-rounded tf32 (raw-bit frags); B cvt at consume.
template <int MODE, int KSTRIDE, int KLEN, int N>
__global__ __launch_bounds__(128, 3)
void moe_wg(const float* __restrict__ A_all, const float* __restrict__ B_all,
            const float* __restrict__ bias_all, float* __restrict__ C_all)
{
    constexpr int NS = KLEN / 16;
    extern __shared__ float sm[];
    const uint32_t smb = smem_u32(sm);

    const int tid  = threadIdx.x;
    const int lane = tid & 31;
    const int wid  = tid >> 5;                 // 0..3 = n-block
    const int e    = blockIdx.y;
    const int n0   = blockIdx.x * 256;
    const int kb   = (MODE == 1 ? blockIdx.z * KLEN : 0);

    const float* Ae = A_all    + (size_t)e * NC * KSTRIDE + kb;
    const float* Bg = B_all    + (size_t)e * KSTRIDE * N + (size_t)kb * N + n0;
    const float* be = bias_all + (size_t)e * N + n0;
    float*       Ce = C_all    + (MODE == 1 ? (size_t)blockIdx.z * NE * NC * N : 0)
                               + (size_t)e * NC * N + n0;

    const int g  = lane >> 2, tg = lane & 3;

    float acc[4][8][4];                         // 128 regs
    #pragma unroll
    for (int i = 0; i < 4; i++)
        #pragma unroll
        for (int j = 0; j < 8; j++)
            #pragma unroll
            for (int k = 0; k < 4; k++) acc[i][j][k] = 0.0f;

    // ---- async stage fill (128 threads): A 256 x 16B, B 1024 x 16B ----
    auto ISSUE = [&](int s) {
        const int buf = s % 3;
        const uint32_t sA = smb + (uint32_t)(buf * STG_W) * 4u;
        const uint32_t sB = sA + A_W * 4u;
        const int k0 = s * 16;
        #pragma unroll
        for (int r = 0; r < 2; r++) {           // A: 64 rows x 16 k
            int idx = r * 128 + tid;
            int row = idx >> 2, c = idx & 3;
            cp16(sA + (uint32_t)(row * AST + c * 4) * 4u,
                 Ae + (size_t)row * KSTRIDE + k0 + c * 4);
        }
        #pragma unroll
        for (int r = 0; r < 8; r++) {           // B: 16 rows x 256 n
            int idx = r * 128 + tid;
            int row = idx >> 6, c = idx & 63;
            cp16(sB + (uint32_t)(row * BST + c * 4) * 4u,
                 Bg + (size_t)(k0 + row) * N + c * 4);
        }
    };

    // ---- consume one stage: warp tile 64x64, two k8 steps ----
    auto COMPUTE = [&](int buf) {
        const float* sAf = sm + buf * STG_W;
        const float* sBf = sAf + A_W;
        #pragma unroll
        for (int h = 0; h < 2; h++) {
            uint32_t A0[4], A1[4], A2[4], A3[4];
            #pragma unroll
            for (int ma = 0; ma < 4; ma++) {
                const float* p = sAf + (ma * 16 + g) * AST + h * 8 + tg;
                A0[ma] = __float_as_uint(p[0]);
                A2[ma] = __float_as_uint(p[4]);
                A1[ma] = __float_as_uint(p[8 * AST]);
                A3[ma] = __float_as_uint(p[8 * AST + 4]);
            }
            #pragma unroll
            for (int na = 0; na < 8; na++) {
                const float* q = sBf + (h * 8 + tg) * BST + wid * 64 + na * 8 + g;
                uint32_t B0 = to_tf32u(q[0]);
                uint32_t B1 = to_tf32u(q[4 * BST]);
                #pragma unroll
                for (int ma = 0; ma < 4; ma++)
                    mma8(acc[ma][na], A0[ma], A1[ma], A2[ma], A3[ma], B0, B1);
            }
        }
    };

    // ---- 3-stage pipeline, single sync per slab ----
    ISSUE(0); CP_COMMIT();
    ISSUE(1); CP_COMMIT();
    CP_WAIT1();                 // stage 0 resident
    __syncthreads();
    for (int s = 0; s < NS; s++) {
        if (s + 2 < NS) ISSUE(s + 2);
        CP_COMMIT();            // uniform group count (may be empty)
        COMPUTE(s % 3);
        CP_WAIT1();             // stage s+1 resident
        __syncthreads();
    }

    // ---- epilogue ----
    if (MODE == 0) {
        float2 bvv[8];
        #pragma unroll
        for (int na = 0; na < 8; na++)
            bvv[na] = *reinterpret_cast<const float2*>(be + wid * 64 + na * 8 + 2 * tg);
        #pragma unroll
        for (int ma = 0; ma < 4; ma++) {
            int row0 = ma * 16 + g;
            #pragma unroll
            for (int na = 0; na < 8; na++) {
                int col = wid * 64 + na * 8 + 2 * tg;
                float v0 = gelu_tanh(acc[ma][na][0] + bvv[na].x);
                float v1 = gelu_tanh(acc[ma][na][1] + bvv[na].y);
                float v2 = gelu_tanh(acc[ma][na][2] + bvv[na].x);
                float v3 = gelu_tanh(acc[ma][na][3] + bvv[na].y);
                float2 w0 = make_float2(__uint_as_float(to_tf32u(v0)),
                                        __uint_as_float(to_tf32u(v1)));
                float2 w1 = make_float2(__uint_as_float(to_tf32u(v2)),
                                        __uint_as_float(to_tf32u(v3)));
                *reinterpret_cast<float2*>(Ce + (size_t)row0 * N + col)       = w0;
                *reinterpret_cast<float2*>(Ce + (size_t)(row0 + 8) * N + col) = w1;
            }
        }
    } else {
        #pragma unroll
        for (int ma = 0; ma < 4; ma++) {
            int row0 = ma * 16 + g;
            #pragma unroll
            for (int na = 0; na < 8; na++) {
                int col = wid * 64 + na * 8 + 2 * tg;
                *reinterpret_cast<float2*>(Ce + (size_t)row0 * N + col) =
                    make_float2(acc[ma][na][0], acc[ma][na][1]);
                *reinterpret_cast<float2*>(Ce + (size_t)(row0 + 8) * N + col) =
                    make_float2(acc[ma][na][2], acc[ma][na][3]);
            }
        }
    }
}

// round x -> tf32 once
__global__ void round_x(const float* __restrict__ x, float* __restrict__ xo) {
    int i = blockIdx.x * blockDim.x + threadIdx.x;
    float4 v = reinterpret_cast<const float4*>(x)[i];
    v.x = __uint_as_float(to_tf32u(v.x));
    v.y = __uint_as_float(to_tf32u(v.y));
    v.z = __uint_as_float(to_tf32u(v.z));
    v.w = __uint_as_float(to_tf32u(v.w));
    reinterpret_cast<float4*>(xo)[i] = v;
}

// out = p0 + p1 + bias (deterministic fixed-order)
__global__ void fixup2(const float* __restrict__ p0, const float* __restrict__ p1,
                       const float* __restrict__ b2, float* __restrict__ out) {
    int i = blockIdx.x * blockDim.x + threadIdx.x;
    int i4 = i * 4;
    int e   = i4 >> 16;
    int col = i4 & (ND - 1);
    float4 a = reinterpret_cast<const float4*>(p0)[i];
    float4 b = reinterpret_cast<const float4*>(p1)[i];
    float4 c = *reinterpret_cast<const float4*>(b2 + (size_t)e * ND + col);
    reinterpret_cast<float4*>(out)[i] =
        make_float4(a.x + b.x + c.x, a.y + b.y + c.y,
                    a.z + b.z + c.z, a.w + b.w + c.w);
}

// ---------------- host launch ----------------
extern "C" void kernel_launch(void* const* d_in, const int* in_sizes, int n_in,
                              void* d_out, int out_size)
{
    (void)in_sizes; (void)n_in; (void)out_size;
    const float* x  = (const float*)d_in[0];
    const float* W1 = (const float*)d_in[1];
    const float* b1 = (const float*)d_in[2];
    const float* W2 = (const float*)d_in[3];
    const float* b2 = (const float*)d_in[4];
    float* out = (float*)d_out;

    float *hbuf = nullptr, *xbuf = nullptr, *pbuf = nullptr;
    cudaGetSymbolAddress((void**)&hbuf, g_h);
    cudaGetSymbolAddress((void**)&xbuf, g_x);
    cudaGetSymbolAddress((void**)&pbuf, g_p);

    const int smem = 3 * STG_W * (int)sizeof(float);   // 66048 B

    cudaFuncSetAttribute((const void*)moe_wg<0, ND, ND, NF>,
                         cudaFuncAttributeMaxDynamicSharedMemorySize, smem);
    cudaFuncSetAttribute((const void*)moe_wg<1, NF, KSPLIT2, ND>,
                         cudaFuncAttributeMaxDynamicSharedMemorySize, smem);

    const int nelem4 = NE * NC * ND / 4;

    // 0) pre-round x
    round_x<<<nelem4 / 256, 256>>>(x, xbuf);
    // 1) h = tf32(gelu(x @ W1 + b1))
    moe_wg<0, ND, ND, NF><<<dim3(NF / 256, NE, 1), 128, smem>>>(xbuf, W1, b1, hbuf);
    // 2) partials: p[z] = h @ W2[z-half]
    moe_wg<1, NF, KSPLIT2, ND><<<dim3(ND / 256, NE, 2), 128, smem>>>(hbuf, W2, b2, pbuf);
    // 3) out = p0 + p1 + b2
    fixup2<<<nelem4 / 256, 256>>>(pbuf, pbuf + (size_t)NE * NC * ND, b2, out);
}

// round 10
// speedup vs baseline: 1.0684x; 1.0684x over previous
#include <cuda_runtime.h>
#include <cstdint>

#define NE 32     // experts
#define NC 64     // rows per expert
#define ND 1024   // d_model
#define NF 4096   // d_ff
#define KSPLIT2 2048              // GEMM2 K-split length

// static scratch (no allocation): h (32MB), rounded x (8MB), GEMM2 partials (16MB)
__device__ float g_h[(size_t)NE * NC * NF];
__device__ float g_x[(size_t)NE * NC * ND];
__device__ float g_p[2][(size_t)NE * NC * ND];

// ---- smem geometry (words): CTA tile 64x256, BK=16, 4 stages ----
#define AST 20                    // A row stride (16 k + 4 pad): frag banks distinct
#define BST 264                   // B row stride (256 n + 8 pad): frag bank = 8tg+g
#define A_W  (64 * AST)           // 1280 words
#define B_W  (16 * BST)           // 4224 words
#define STG_W (A_W + B_W)         // 5504 words = 22016 B; x4 = 88064 B -> 2 CTAs/SM

__device__ __forceinline__ uint32_t smem_u32(const void* p) {
    uint32_t a;
    asm("{ .reg .u64 t; cvta.to.shared.u64 t, %1; cvt.u32.u64 %0, t; }" : "=r"(a) : "l"(p));
    return a;
}
__device__ __forceinline__ uint32_t to_tf32u(float x) {
    uint32_t y; asm("cvt.rna.tf32.f32 %0, %1;" : "=r"(y) : "f"(x)); return y;
}
__device__ __forceinline__ float tanh_fast(float x) {
    float y; asm("tanh.approx.f32 %0, %1;" : "=f"(y) : "f"(x)); return y;
}
__device__ __forceinline__ float gelu_tanh(float v) {
    const float c0 = 0.7978845608028654f;
    const float c1 = 0.044715f;
    float u = c0 * fmaf(c1 * v * v, v, v);
    return 0.5f * v * (1.0f + tanh_fast(u));
}
__device__ __forceinline__ void cp16(uint32_t dst, const void* src) {
    asm volatile("cp.async.cg.shared.global [%0], [%1], 16;" :: "r"(dst), "l"(src));
}
#define CP_COMMIT() asm volatile("cp.async.commit_group;" ::: "memory")
#define CP_WAIT2()  asm volatile("cp.async.wait_group 2;"  ::: "memory")

__device__ __forceinline__ void mma8(float (&c)[4],
                                     uint32_t a0, uint32_t a1, uint32_t a2, uint32_t a3,
                                     uint32_t b0, uint32_t b1) {
    asm volatile("mma.sync.aligned.m16n8k8.row.col.f32.tf32.tf32.f32 "
                 "{%0,%1,%2,%3}, {%4,%5,%6,%7}, {%8,%9}, {%0,%1,%2,%3};"
                 : "+f"(c[0]), "+f"(c[1]), "+f"(c[2]), "+f"(c[3])
                 : "r"(a0), "r"(a1), "r"(a2), "r"(a3), "r"(b0), "r"(b1));
}

// Unified grouped-GEMM: CTA tile 64x256, 4 warps, warp tile 64x64, BK=16,
// 4-stage cp.async pipeline, wait_group 2, ONE __syncthreads per slab.
// MODE 0: C = tf32round(gelu(A@B + bias))   (GEMM1 -> g_h)
// MODE 1: C = A@B partial (K-split via blockIdx.z)  (GEMM2 -> g_p)
// A pre-rounded tf32 (raw-bit frags); B cvt at consume.
template <int MODE, int KSTRIDE, int KLEN, int N>
__global__ __launch_bounds__(128, 2)
void moe_wg(const float* __restrict__ A_all, const float* __restrict__ B_all,
            const float* __restrict__ bias_all, float* __restrict__ C_all)
{
    constexpr int NS = KLEN / 16;
    extern __shared__ float sm[];
    const uint32_t smb = smem_u32(sm);

    const int tid  = threadIdx.x;
    const int lane = tid & 31;
    const int wid  = tid >> 5;                 // 0..3 = n-block
    const int e    = blockIdx.y;
    const int n0   = blockIdx.x * 256;
    const int kb   = (MODE == 1 ? blockIdx.z * KLEN : 0);

    const float* Ae = A_all    + (size_t)e * NC * KSTRIDE + kb;
    const float* Bg = B_all    + (size_t)e * KSTRIDE * N + (size_t)kb * N + n0;
    const float* be = bias_all + (size_t)e * N + n0;
    float*       Ce = C_all    + (MODE == 1 ? (size_t)blockIdx.z * NE * NC * N : 0)
                               + (size_t)e * NC * N + n0;

    const int g  = lane >> 2, tg = lane & 3;

    float acc[4][8][4];                         // 128 regs
    #pragma unroll
    for (int i = 0; i < 4; i++)
        #pragma unroll
        for (int j = 0; j < 8; j++)
            #pragma unroll
            for (int k = 0; k < 4; k++) acc[i][j][k] = 0.0f;

    // ---- async stage fill (128 threads): A 256 x 16B, B 1024 x 16B ----
    auto ISSUE = [&](int s) {
        const int buf = s & 3;
        const uint32_t sA = smb + (uint32_t)(buf * STG_W) * 4u;
        const uint32_t sB = sA + A_W * 4u;
        const int k0 = s * 16;
        #pragma unroll
        for (int r = 0; r < 2; r++) {           // A: 64 rows x 16 k
            int idx = r * 128 + tid;
            int row = idx >> 2, c = idx & 3;
            cp16(sA + (uint32_t)(row * AST + c * 4) * 4u,
                 Ae + (size_t)row * KSTRIDE + k0 + c * 4);
        }
        #pragma unroll
        for (int r = 0; r < 8; r++) {           // B: 16 rows x 256 n
            int idx = r * 128 + tid;
            int row = idx >> 6, c = idx & 63;
            cp16(sB + (uint32_t)(row * BST + c * 4) * 4u,
                 Bg + (size_t)(k0 + row) * N + c * 4);
        }
    };

    // ---- consume one stage: warp tile 64x64, two k8 steps ----
    auto COMPUTE = [&](int buf) {
        const float* sAf = sm + buf * STG_W;
        const float* sBf = sAf + A_W;
        #pragma unroll
        for (int h = 0; h < 2; h++) {
            uint32_t A0[4], A1[4], A2[4], A3[4];
            #pragma unroll
            for (int ma = 0; ma < 4; ma++) {
                const float* p = sAf + (ma * 16 + g) * AST + h * 8 + tg;
                A0[ma] = __float_as_uint(p[0]);
                A2[ma] = __float_as_uint(p[4]);
                A1[ma] = __float_as_uint(p[8 * AST]);
                A3[ma] = __float_as_uint(p[8 * AST + 4]);
            }
            #pragma unroll
            for (int na = 0; na < 8; na++) {
                const float* q = sBf + (h * 8 + tg) * BST + wid * 64 + na * 8 + g;
                uint32_t B0 = to_tf32u(q[0]);
                uint32_t B1 = to_tf32u(q[4 * BST]);
                #pragma unroll
                for (int ma = 0; ma < 4; ma++)
                    mma8(acc[ma][na], A0[ma], A1[ma], A2[ma], A3[ma], B0, B1);
            }
        }
    };

    // ---- 4-stage pipeline, wait_group 2, single sync per slab ----
    ISSUE(0); CP_COMMIT();
    ISSUE(1); CP_COMMIT();
    ISSUE(2); CP_COMMIT();
    CP_WAIT2();                 // stage 0 resident; 1,2 in flight
    __syncthreads();
    for (int s = 0; s < NS; s++) {
        if (s + 3 < NS) ISSUE(s + 3);
        CP_COMMIT();            // uniform group count (may be empty)
        COMPUTE(s & 3);
        CP_WAIT2();             // stage s+1 resident; s+2, s+3 in flight
        __syncthreads();
    }

    // ---- epilogue ----
    if (MODE == 0) {
        float2 bvv[8];
        #pragma unroll
        for (int na = 0; na < 8; na++)
            bvv[na] = *reinterpret_cast<const float2*>(be + wid * 64 + na * 8 + 2 * tg);
        #pragma unroll
        for (int ma = 0; ma < 4; ma++) {
            int row0 = ma * 16 + g;
            #pragma unroll
            for (int na = 0; na < 8; na++) {
                int col = wid * 64 + na * 8 + 2 * tg;
                float v0 = gelu_tanh(acc[ma][na][0] + bvv[na].x);
                float v1 = gelu_tanh(acc[ma][na][1] + bvv[na].y);
                float v2 = gelu_tanh(acc[ma][na][2] + bvv[na].x);
                float v3 = gelu_tanh(acc[ma][na][3] + bvv[na].y);
                float2 w0 = make_float2(__uint_as_float(to_tf32u(v0)),
                                        __uint_as_float(to_tf32u(v1)));
                float2 w1 = make_float2(__uint_as_float(to_tf32u(v2)),
                                        __uint_as_float(to_tf32u(v3)));
                *reinterpret_cast<float2*>(Ce + (size_t)row0 * N + col)       = w0;
                *reinterpret_cast<float2*>(Ce + (size_t)(row0 + 8) * N + col) = w1;
            }
        }
    } else {
        #pragma unroll
        for (int ma = 0; ma < 4; ma++) {
            int row0 = ma * 16 + g;
            #pragma unroll
            for (int na = 0; na < 8; na++) {
                int col = wid * 64 + na * 8 + 2 * tg;
                *reinterpret_cast<float2*>(Ce + (size_t)row0 * N + col) =
                    make_float2(acc[ma][na][0], acc[ma][na][1]);
                *reinterpret_cast<float2*>(Ce + (size_t)(row0 + 8) * N + col) =
                    make_float2(acc[ma][na][2], acc[ma][na][3]);
            }
        }
    }
}

// round x -> tf32 once
__global__ void round_x(const float* __restrict__ x, float* __restrict__ xo) {
    int i = blockIdx.x * blockDim.x + threadIdx.x;
    float4 v = reinterpret_cast<const float4*>(x)[i];
    v.x = __uint_as_float(to_tf32u(v.x));
    v.y = __uint_as_float(to_tf32u(v.y));
    v.z = __uint_as_float(to_tf32u(v.z));
    v.w = __uint_as_float(to_tf32u(v.w));
    reinterpret_cast<float4*>(xo)[i] = v;
}

// out = p0 + p1 + bias (deterministic fixed-order)
__global__ void fixup2(const float* __restrict__ p0, const float* __restrict__ p1,
                       const float* __restrict__ b2, float* __restrict__ out) {
    int i = blockIdx.x * blockDim.x + threadIdx.x;
    int i4 = i * 4;
    int e   = i4 >> 16;
    int col = i4 & (ND - 1);
    float4 a = reinterpret_cast<const float4*>(p0)[i];
    float4 b = reinterpret_cast<const float4*>(p1)[i];
    float4 c = *reinterpret_cast<const float4*>(b2 + (size_t)e * ND + col);
    reinterpret_cast<float4*>(out)[i] =
        make_float4(a.x + b.x + c.x, a.y + b.y + c.y,
                    a.z + b.z + c.z, a.w + b.w + c.w);
}

// ---------------- host launch ----------------
extern "C" void kernel_launch(void* const* d_in, const int* in_sizes, int n_in,
                              void* d_out, int out_size)
{
    (void)in_sizes; (void)n_in; (void)out_size;
    const float* x  = (const float*)d_in[0];
    const float* W1 = (const float*)d_in[1];
    const float* b1 = (const float*)d_in[2];
    const float* W2 = (const float*)d_in[3];
    const float* b2 = (const float*)d_in[4];
    float* out = (float*)d_out;

    float *hbuf = nullptr, *xbuf = nullptr, *pbuf = nullptr;
    cudaGetSymbolAddress((void**)&hbuf, g_h);
    cudaGetSymbolAddress((void**)&xbuf, g_x);
    cudaGetSymbolAddress((void**)&pbuf, g_p);

    const int smem = 4 * STG_W * (int)sizeof(float);   // 88064 B

    cudaFuncSetAttribute((const void*)moe_wg<0, ND, ND, NF>,
                         cudaFuncAttributeMaxDynamicSharedMemorySize, smem);
    cudaFuncSetAttribute((const void*)moe_wg<1, NF, KSPLIT2, ND>,
                         cudaFuncAttributeMaxDynamicSharedMemorySize, smem);

    const int nelem4 = NE * NC * ND / 4;

    // 0) pre-round x
    round_x<<<nelem4 / 256, 256>>>(x, xbuf);
    // 1) h = tf32(gelu(x @ W1 + b1))
    moe_wg<0, ND, ND, NF><<<dim3(NF / 256, NE, 1), 128, smem>>>(xbuf, W1, b1, hbuf);
    // 2) partials: p[z] = h @ W2[z-half]
    moe_wg<1, NF, KSPLIT2, ND><<<dim3(ND / 256, NE, 2), 128, smem>>>(hbuf, W2, b2, pbuf);
    // 3) out = p0 + p1 + b2
    fixup2<<<nelem4 / 256, 256>>>(pbuf, pbuf + (size_t)NE * NC * ND, b2, out);
}

// round 11
// speedup vs baseline: 1.1532x; 1.0794x over previous
#include <cuda_runtime.h>
#include <cstdint>

#define NE 32     // experts
#define NC 64     // rows per expert
#define ND 1024   // d_model
#define NF 4096   // d_ff
#define KSPLIT2 2048              // GEMM2 K-split length

// static scratch (no allocation): h (32MB), rounded x (8MB), GEMM2 partials (16MB)
__device__ float g_h[(size_t)NE * NC * NF];
__device__ float g_x[(size_t)NE * NC * ND];
__device__ float g_p[2][(size_t)NE * NC * ND];

// ---- smem geometry (words): CTA tile 64x256, BK=32, 2 stages (r8-proven) ----
#define AST 36                    // A row stride (32 k + 4 pad)
#define BST 264                   // B row stride (256 n + 8 pad): frag bank = 8tg+g
#define A_W  (64 * AST)           // 2304 words
#define B_W  (32 * BST)           // 8448 words
#define STG_W (A_W + B_W)         // 10752 words = 43008 B; x2 = 86016 B -> 2 CTAs/SM

__device__ __forceinline__ uint32_t smem_u32(const void* p) {
    uint32_t a;
    asm("{ .reg .u64 t; cvta.to.shared.u64 t, %1; cvt.u32.u64 %0, t; }" : "=r"(a) : "l"(p));
    return a;
}
__device__ __forceinline__ uint32_t to_tf32u(float x) {
    uint32_t y; asm("cvt.rna.tf32.f32 %0, %1;" : "=r"(y) : "f"(x)); return y;
}
__device__ __forceinline__ float tanh_fast(float x) {
    float y; asm("tanh.approx.f32 %0, %1;" : "=f"(y) : "f"(x)); return y;
}
__device__ __forceinline__ float gelu_tanh(float v) {
    const float c0 = 0.7978845608028654f;
    const float c1 = 0.044715f;
    float u = c0 * fmaf(c1 * v * v, v, v);
    return 0.5f * v * (1.0f + tanh_fast(u));
}
__device__ __forceinline__ void cp16(uint32_t dst, const void* src) {
    asm volatile("cp.async.cg.shared.global [%0], [%1], 16;" :: "r"(dst), "l"(src));
}
#define CP_COMMIT() asm volatile("cp.async.commit_group;" ::: "memory")
#define CP_WAIT1()  asm volatile("cp.async.wait_group 1;"  ::: "memory")

__device__ __forceinline__ void mma8(float (&c)[4],
                                     uint32_t a0, uint32_t a1, uint32_t a2, uint32_t a3,
                                     uint32_t b0, uint32_t b1) {
    asm volatile("mma.sync.aligned.m16n8k8.row.col.f32.tf32.tf32.f32 "
                 "{%0,%1,%2,%3}, {%4,%5,%6,%7}, {%8,%9}, {%0,%1,%2,%3};"
                 : "+f"(c[0]), "+f"(c[1]), "+f"(c[2]), "+f"(c[3])
                 : "r"(a0), "r"(a1), "r"(a2), "r"(a3), "r"(b0), "r"(b1));
}

// Unified grouped-GEMM: CTA tile 64x256, 4 warps, warp tile 64x64, BK=32,
// 2-stage cp.async pipeline + DOUBLE-BUFFERED FRAGMENT REGISTERS:
// fragment loads for k-step h+1 overlap the 32 MMAs of k-step h.
// MODE 0: C = tf32round(gelu(A@B + bias))   (GEMM1 -> g_h)
// MODE 1: C = A@B partial (K-split via blockIdx.z)  (GEMM2 -> g_p)
// A pre-rounded tf32 (raw-bit frags); B cvt at consume.
template <int MODE, int KSTRIDE, int KLEN, int N>
__global__ __launch_bounds__(128, 2)
void moe_wg(const float* __restrict__ A_all, const float* __restrict__ B_all,
            const float* __restrict__ bias_all, float* __restrict__ C_all)
{
    constexpr int NS = KLEN / 32;
    extern __shared__ float sm[];
    const uint32_t smb = smem_u32(sm);

    const int tid  = threadIdx.x;
    const int lane = tid & 31;
    const int wid  = tid >> 5;                 // 0..3 = n-block
    const int e    = blockIdx.y;
    const int n0   = blockIdx.x * 256;
    const int kb   = (MODE == 1 ? blockIdx.z * KLEN : 0);

    const float* Ae = A_all    + (size_t)e * NC * KSTRIDE + kb;
    const float* Bg = B_all    + (size_t)e * KSTRIDE * N + (size_t)kb * N + n0;
    const float* be = bias_all + (size_t)e * N + n0;
    float*       Ce = C_all    + (MODE == 1 ? (size_t)blockIdx.z * NE * NC * N : 0)
                               + (size_t)e * NC * N + n0;

    const int g  = lane >> 2, tg = lane & 3;

    float acc[4][8][4];                         // 128 regs
    #pragma unroll
    for (int i = 0; i < 4; i++)
        #pragma unroll
        for (int j = 0; j < 8; j++)
            #pragma unroll
            for (int k = 0; k < 4; k++) acc[i][j][k] = 0.0f;

    // ---- async stage fill (128 threads): A 512 x 16B, B 2048 x 16B ----
    auto ISSUE = [&](int s) {
        const int buf = s & 1;
        const uint32_t sA = smb + (uint32_t)(buf * STG_W) * 4u;
        const uint32_t sB = sA + A_W * 4u;
        const int k0 = s * 32;
        #pragma unroll
        for (int r = 0; r < 4; r++) {           // A: 64 rows x 32 k
            int idx = r * 128 + tid;
            int row = idx >> 3, c = idx & 7;
            cp16(sA + (uint32_t)(row * AST + c * 4) * 4u,
                 Ae + (size_t)row * KSTRIDE + k0 + c * 4);
        }
        #pragma unroll
        for (int r = 0; r < 16; r++) {          // B: 32 rows x 256 n
            int idx = r * 128 + tid;
            int row = idx >> 6, c = idx & 63;
            cp16(sB + (uint32_t)(row * BST + c * 4) * 4u,
                 Bg + (size_t)(k0 + row) * N + c * 4);
        }
    };

    // double-buffered fragment registers (64 regs)
    uint32_t fA0[2][4], fA1[2][4], fA2[2][4], fA3[2][4];
    uint32_t fB0[2][8], fB1[2][8];

    // ---- consume one stage: warp tile 64x64, 4 k8-step pairs, frag pipelining ----
    auto COMPUTE = [&](int buf) {
        const float* sAf = sm + buf * STG_W;
        const float* sBf = sAf + A_W;

        auto LOADF = [&](int h, int d) {
            #pragma unroll
            for (int ma = 0; ma < 4; ma++) {
                const float* p = sAf + (ma * 16 + g) * AST + h * 8 + tg;
                fA0[d][ma] = __float_as_uint(p[0]);
                fA2[d][ma] = __float_as_uint(p[4]);
                fA1[d][ma] = __float_as_uint(p[8 * AST]);
                fA3[d][ma] = __float_as_uint(p[8 * AST + 4]);
            }
            #pragma unroll
            for (int na = 0; na < 8; na++) {
                const float* q = sBf + (h * 8 + tg) * BST + wid * 64 + na * 8 + g;
                fB0[d][na] = to_tf32u(q[0]);
                fB1[d][na] = to_tf32u(q[4 * BST]);
            }
        };

        LOADF(0, 0);
        #pragma unroll
        for (int h = 0; h < 4; h++) {
            const int cur = h & 1;
            if (h < 3) LOADF(h + 1, cur ^ 1);   // overlap loads(h+1) with MMAs(h)
            #pragma unroll
            for (int na = 0; na < 8; na++)
                #pragma unroll
                for (int ma = 0; ma < 4; ma++)
                    mma8(acc[ma][na],
                         fA0[cur][ma], fA1[cur][ma], fA2[cur][ma], fA3[cur][ma],
                         fB0[cur][na], fB1[cur][na]);
        }
    };

    // ---- 2-stage pipeline (r8 structure) ----
    ISSUE(0); CP_COMMIT();
    ISSUE(1); CP_COMMIT();
    for (int s = 0; s < NS; s++) {
        CP_WAIT1();
        __syncthreads();
        COMPUTE(s & 1);
        __syncthreads();
        if (s + 2 < NS) ISSUE(s + 2);
        CP_COMMIT();
    }

    // ---- epilogue ----
    if (MODE == 0) {
        float2 bvv[8];
        #pragma unroll
        for (int na = 0; na < 8; na++)
            bvv[na] = *reinterpret_cast<const float2*>(be + wid * 64 + na * 8 + 2 * tg);
        #pragma unroll
        for (int ma = 0; ma < 4; ma++) {
            int row0 = ma * 16 + g;
            #pragma unroll
            for (int na = 0; na < 8; na++) {
                int col = wid * 64 + na * 8 + 2 * tg;
                float v0 = gelu_tanh(acc[ma][na][0] + bvv[na].x);
                float v1 = gelu_tanh(acc[ma][na][1] + bvv[na].y);
                float v2 = gelu_tanh(acc[ma][na][2] + bvv[na].x);
                float v3 = gelu_tanh(acc[ma][na][3] + bvv[na].y);
                float2 w0 = make_float2(__uint_as_float(to_tf32u(v0)),
                                        __uint_as_float(to_tf32u(v1)));
                float2 w1 = make_float2(__uint_as_float(to_tf32u(v2)),
                                        __uint_as_float(to_tf32u(v3)));
                *reinterpret_cast<float2*>(Ce + (size_t)row0 * N + col)       = w0;
                *reinterpret_cast<float2*>(Ce + (size_t)(row0 + 8) * N + col) = w1;
            }
        }
    } else {
        #pragma unroll
        for (int ma = 0; ma < 4; ma++) {
            int row0 = ma * 16 + g;
            #pragma unroll
            for (int na = 0; na < 8; na++) {
                int col = wid * 64 + na * 8 + 2 * tg;
                *reinterpret_cast<float2*>(Ce + (size_t)row0 * N + col) =
                    make_float2(acc[ma][na][0], acc[ma][na][1]);
                *reinterpret_cast<float2*>(Ce + (size_t)(row0 + 8) * N + col) =
                    make_float2(acc[ma][na][2], acc[ma][na][3]);
            }
        }
    }
}

// round x -> tf32 once
__global__ void round_x(const float* __restrict__ x, float* __restrict__ xo) {
    int i = blockIdx.x * blockDim.x + threadIdx.x;
    float4 v = reinterpret_cast<const float4*>(x)[i];
    v.x = __uint_as_float(to_tf32u(v.x));
    v.y = __uint_as_float(to_tf32u(v.y));
    v.z = __uint_as_float(to_tf32u(v.z));
    v.w = __uint_as_float(to_tf32u(v.w));
    reinterpret_cast<float4*>(xo)[i] = v;
}

// out = p0 + p1 + bias (deterministic fixed-order)
__global__ void fixup2(const float* __restrict__ p0, const float* __restrict__ p1,
                       const float* __restrict__ b2, float* __restrict__ out) {
    int i = blockIdx.x * blockDim.x + threadIdx.x;
    int i4 = i * 4;
    int e   = i4 >> 16;
    int col = i4 & (ND - 1);
    float4 a = reinterpret_cast<const float4*>(p0)[i];
    float4 b = reinterpret_cast<const float4*>(p1)[i];
    float4 c = *reinterpret_cast<const float4*>(b2 + (size_t)e * ND + col);
    reinterpret_cast<float4*>(out)[i] =
        make_float4(a.x + b.x + c.x, a.y + b.y + c.y,
                    a.z + b.z + c.z, a.w + b.w + c.w);
}

// ---------------- host launch ----------------
extern "C" void kernel_launch(void* const* d_in, const int* in_sizes, int n_in,
                              void* d_out, int out_size)
{
    (void)in_sizes; (void)n_in; (void)out_size;
    const float* x  = (const float*)d_in[0];
    const float* W1 = (const float*)d_in[1];
    const float* b1 = (const float*)d_in[2];
    const float* W2 = (const float*)d_in[3];
    const float* b2 = (const float*)d_in[4];
    float* out = (float*)d_out;

    float *hbuf = nullptr, *xbuf = nullptr, *pbuf = nullptr;
    cudaGetSymbolAddress((void**)&hbuf, g_h);
    cudaGetSymbolAddress((void**)&xbuf, g_x);
    cudaGetSymbolAddress((void**)&pbuf, g_p);

    const int smem = 2 * STG_W * (int)sizeof(float);   // 86016 B

    cudaFuncSetAttribute((const void*)moe_wg<0, ND, ND, NF>,
                         cudaFuncAttributeMaxDynamicSharedMemorySize, smem);
    cudaFuncSetAttribute((const void*)moe_wg<1, NF, KSPLIT2, ND>,
                         cudaFuncAttributeMaxDynamicSharedMemorySize, smem);

    const int nelem4 = NE * NC * ND / 4;

    // 0) pre-round x
    round_x<<<nelem4 / 256, 256>>>(x, xbuf);
    // 1) h = tf32(gelu(x @ W1 + b1))
    moe_wg<0, ND, ND, NF><<<dim3(NF / 256, NE, 1), 128, smem>>>(xbuf, W1, b1, hbuf);
    // 2) partials: p[z] = h @ W2[z-half]
    moe_wg<1, NF, KSPLIT2, ND><<<dim3(ND / 256, NE, 2), 128, smem>>>(hbuf, W2, b2, pbuf);
    // 3) out = p0 + p1 + b2
    fixup2<<<nelem4 / 256, 256>>>(pbuf, pbuf + (size_t)NE * NC * ND, b2, out);
}